// round 6
// baseline (speedup 1.0000x reference)
#include <cuda_runtime.h>
#include <cuda_bf16.h>

// ---- static problem config ----
#define NIMG 32
#define HH   1024
#define WW   1024
#define BHW  16                 // pool window
#define BSTR 14                 // block stride
#define BC   73                 // blocks per spatial dim
#define BC2  (BC*BC)            // 5329
#define NROW (NIMG*BC)          // 2336  (n, bh) row-blocks
#define NBLK (NROW*BC)          // 170528 total blocks
#define OUT_ELEMS (NBLK*3)      // 511584 floats = 127896 float4 (exact)
#define OUT_VEC4  (OUT_ELEMS/4)
#define THRESH 0.9f

#define GWIN   8                                  // bh windows per strip
#define NSTRIP ((BC + GWIN - 1) / GWIN)           // 10 strips per image
#define W4     (WW/4)

// scratch (device globals — no allocation allowed)
__device__ unsigned g_bitmap[NROW * 3];   // 96-bit active mask per (n,bh) row
__device__ unsigned g_count[NROW];        // popcount per row
__device__ unsigned g_offset[NROW];       // exclusive prefix of counts
__device__ unsigned g_total;              // total active blocks

__device__ __forceinline__ float4 fmax4(float4 a, float4 b)
{
    return make_float4(fmaxf(a.x, b.x), fmaxf(a.y, b.y),
                       fmaxf(a.z, b.z), fmaxf(a.w, b.w));
}

// ---------------------------------------------------------------------------
// K1: strip pooling. One CTA per (n, strip of GWIN consecutive bh windows).
// Window bh covers padded rows [14bh, 14bh+16) -> unpadded [14bh-1, 14bh+15).
// Adjacent windows share exactly rows {14bh-1, 14bh}; the CTA carries their
// column max in registers, so each interior row is loaded once. Per window:
// 14 fully-unrolled float4 loads per thread (high MLP), vertical max ->
// smem, horizontal max over 73 positions, ballot into a 96-bit bitmap.
// Zero is the exact identity (zero padding, mask values in [0,1)).
// ---------------------------------------------------------------------------
__global__ __launch_bounds__(256) void pool_kernel(const float* __restrict__ mask)
{
    const int cta = blockIdx.x;
    const int n   = cta / NSTRIP;
    const int s   = cta % NSTRIP;
    const int bh0 = s * GWIN;
    const int nw  = (BC - bh0 < GWIN) ? (BC - bh0) : GWIN;
    const int tid = threadIdx.x;

    __shared__ float sv[WW];
    __shared__ unsigned sbm[3];

    const float4* base = (const float4*)(mask + (size_t)n * HH * WW) + tid;

    // carry = column max of the two overlap rows {14*bh0-1, 14*bh0}
    float4 carry = make_float4(0.f, 0.f, 0.f, 0.f);
    {
        const int r0 = bh0 * BSTR - 1;           // -1 only when bh0 == 0
        if (r0 >= 0) carry = fmax4(carry, base[r0 * W4]);
        carry = fmax4(carry, base[(bh0 * BSTR) * W4]);
    }

    for (int j = 0; j < nw; ++j) {
        const int bh    = bh0 + j;
        const int rbase = bh * BSTR;             // rows rbase+1 .. rbase+14 are new
        float4 acc = carry;
        float4 tl  = make_float4(0.f, 0.f, 0.f, 0.f);
        #pragma unroll
        for (int i = 1; i <= 14; ++i) {          // 14*bh+14 <= 1022 < HH: no clip
            float4 x = base[(rbase + i) * W4];
            acc = fmax4(acc, x);
            if (i >= 13) tl = fmax4(tl, x);      // overlap rows for next window
        }
        carry = tl;

        sv[4 * tid + 0] = acc.x;
        sv[4 * tid + 1] = acc.y;
        sv[4 * tid + 2] = acc.z;
        sv[4 * tid + 3] = acc.w;
        __syncthreads();

        if (tid < 96) {                          // warps 0,1,2
            float m = 0.f;
            if (tid < BC) {
                const int w0 = tid * BSTR - 1;
                const int ws = (w0 < 0) ? 0 : w0;
                const int we = (w0 + BHW < WW) ? (w0 + BHW) : WW;
                for (int w = ws; w < we; ++w) m = fmaxf(m, sv[w]);
            }
            unsigned b = __ballot_sync(0xFFFFFFFFu, m > THRESH);
            if ((tid & 31) == 0) sbm[tid >> 5] = b;
        }
        __syncthreads();

        const int row = n * BC + bh;
        if (tid < 3) g_bitmap[row * 3 + tid] = sbm[tid];
        if (tid == 0)
            g_count[row] = (unsigned)(__popc(sbm[0]) + __popc(sbm[1]) + __popc(sbm[2]));
        // next iteration rewrites sv only after this barrierless region's
        // readers (tid<96) already passed the sync above; sbm reads are
        // ordered by that same sync.
    }
}

// ---------------------------------------------------------------------------
// K2: single-CTA exclusive scan over the 2336 per-row counts; emits g_total.
// ---------------------------------------------------------------------------
#define SCAN_T   256
#define SCAN_PER ((NROW + SCAN_T - 1) / SCAN_T)   // 10

__global__ __launch_bounds__(SCAN_T) void scan_kernel()
{
    __shared__ unsigned partial[SCAN_T];
    const int tid = threadIdx.x;

    unsigned local[SCAN_PER];
    unsigned sum = 0;
    #pragma unroll
    for (int i = 0; i < SCAN_PER; ++i) {
        int idx = tid * SCAN_PER + i;
        unsigned v = (idx < NROW) ? g_count[idx] : 0u;
        local[i] = sum;                 // exclusive within my chunk
        sum += v;
    }
    partial[tid] = sum;
    __syncthreads();

    for (int off = 1; off < SCAN_T; off <<= 1) {
        unsigned t = (tid >= off) ? partial[tid - off] : 0u;
        __syncthreads();
        partial[tid] += t;
        __syncthreads();
    }
    unsigned base = (tid > 0) ? partial[tid - 1] : 0u;

    #pragma unroll
    for (int i = 0; i < SCAN_PER; ++i) {
        int idx = tid * SCAN_PER + i;
        if (idx < NROW) g_offset[idx] = base + local[i];
    }
    if (tid == SCAN_T - 1) g_total = partial[tid];
}

// ---------------------------------------------------------------------------
// Position -> (n, bh, bw) resolution.
// Fast path (total == NBLK): identity divmod. General path: binary search
// last row with offset <= p, then select the rank-th set bit of the bitmap.
// ---------------------------------------------------------------------------
__device__ __forceinline__ int nth_set_bit(unsigned w, int n)  // n-th (0-based)
{
    return (int)__fns(w, 0, n + 1);
}

__device__ __forceinline__ void resolve_pos(unsigned p, unsigned total,
                                            float* t /*[3]*/)
{
    if (p >= total) { t[0] = -1.f; t[1] = -1.f; t[2] = -1.f; return; }

    if (total == NBLK) {   // dense: active block index == block index
        unsigned n = p / BC2;
        unsigned r = p - n * BC2;
        t[0] = (float)n;
        t[1] = (float)(r / BC);
        t[2] = (float)(r % BC);
        return;
    }

    int lo = 0, hi = NROW - 1;
    while (lo < hi) {
        int mid = (lo + hi + 1) >> 1;
        if (g_offset[mid] <= p) lo = mid; else hi = mid - 1;
    }
    int row = lo;
    int rank = (int)(p - g_offset[row]);

    unsigned w0 = g_bitmap[row * 3 + 0];
    unsigned w1 = g_bitmap[row * 3 + 1];
    unsigned w2 = g_bitmap[row * 3 + 2];
    int c0 = __popc(w0), c1 = __popc(w1);
    int bw;
    if (rank < c0)            bw = nth_set_bit(w0, rank);
    else if (rank - c0 < c1)  bw = 32 + nth_set_bit(w1, rank - c0);
    else                      bw = 64 + nth_set_bit(w2, rank - c0 - c1);

    t[0] = (float)(row / BC);
    t[1] = (float)(row % BC);
    t[2] = (float)bw;
}

// ---------------------------------------------------------------------------
// K3: output-driven write. One thread per float4 output slot (4 elements,
// spanning at most 2 consecutive positions). Dense coalesced 16B stores;
// -1 tail handled in the same pass — no fill kernel.
// ---------------------------------------------------------------------------
__global__ __launch_bounds__(256) void write_kernel(float4* __restrict__ out)
{
    const int slot = blockIdx.x * 256 + threadIdx.x;
    if (slot >= OUT_VEC4) return;

    const unsigned total = g_total;
    const unsigned e0 = (unsigned)slot * 4u;
    const unsigned p0 = e0 / 3u;

    float t0[3], t1[3];
    resolve_pos(p0, total, t0);
    resolve_pos(p0 + 1u, total, t1);

    float v[4];
    #pragma unroll
    for (int k = 0; k < 4; ++k) {
        unsigned e = e0 + (unsigned)k;
        unsigned p = e / 3u;
        unsigned c = e - p * 3u;
        v[k] = (p == p0) ? t0[c] : t1[c];
    }
    out[slot] = make_float4(v[0], v[1], v[2], v[3]);
}

// ---------------------------------------------------------------------------
extern "C" void kernel_launch(void* const* d_in, const int* in_sizes, int n_in,
                              void* d_out, int out_size)
{
    const float* mask = (const float*)d_in[0];

    pool_kernel<<<NIMG * NSTRIP, 256>>>(mask);
    scan_kernel<<<1, SCAN_T>>>();
    write_kernel<<<(OUT_VEC4 + 255) / 256, 256>>>((float4*)d_out);
}

// round 7
// speedup vs baseline: 1.4476x; 1.4476x over previous
#include <cuda_runtime.h>
#include <cuda_bf16.h>

// ---- static problem config ----
#define NIMG 32
#define HH   1024
#define WW   1024
#define BHW  16                 // pool window
#define BSTR 14                 // block stride
#define BC   73                 // blocks per spatial dim
#define BC2  (BC*BC)            // 5329
#define NROW (NIMG*BC)          // 2336  (n, bh) row-blocks
#define NBLK (NROW*BC)          // 170528 total blocks
#define OUT_ELEMS (NBLK*3)      // 511584 floats = 127896 float4 (exact)
#define OUT_VEC4  (OUT_ELEMS/4)
#define THRESH 0.9f
#define W4     (WW/4)

// scratch (device globals — no allocation allowed)
__device__ unsigned g_bitmap[NROW * 3];   // 96-bit active mask per (n,bh) row
__device__ unsigned g_count[NROW];        // popcount per row
__device__ unsigned g_offset[NROW];       // exclusive prefix of counts
__device__ unsigned g_total;              // total active blocks

__device__ __forceinline__ float4 ldcs4(const float4* p)
{
    return __ldcs(p);            // streaming (evict-first) 16B load
}

__device__ __forceinline__ float4 fmax4(float4 a, float4 b)
{
    return make_float4(fmaxf(a.x, b.x), fmaxf(a.y, b.y),
                       fmaxf(a.z, b.z), fmaxf(a.w, b.w));
}

// ---------------------------------------------------------------------------
// K1: one CTA per (n, bh). Window bh covers padded rows [14bh, 14bh+16) ->
// unpadded [14bh-1, 14bh+15). Since 14bh+15 <= 1023, only bh=0 clips (top).
// Each of 256 threads owns 4 columns: 15 unconditional + 1 predicated
// fully-unrolled float4 streaming loads (front-batched, MLP=16), vertical
// max -> smem; warps 0-2 do the 73 horizontal maxima and ballot into a
// 96-bit bitmap + count. Zero is the exact identity (zero padding,
// mask values in [0,1)).
// ---------------------------------------------------------------------------
__global__ __launch_bounds__(256) void pool_kernel(const float* __restrict__ mask)
{
    const int cta = blockIdx.x;          // n*BC + bh
    const int n   = cta / BC;
    const int bh  = cta % BC;
    const int tid = threadIdx.x;

    __shared__ float sv[WW];
    __shared__ unsigned sbm[3];

    // rows hs .. hs+14 are always in-bounds; row hs+15 exists iff bh > 0
    const int h0 = bh * BSTR - 1;
    const int hs = (h0 < 0) ? 0 : h0;

    const float4* p = (const float4*)(mask + (size_t)n * HH * WW) + hs * W4 + tid;

    float4 r[16];
    #pragma unroll
    for (int i = 0; i < 15; ++i)
        r[i] = ldcs4(p + i * W4);
    r[15] = (bh > 0) ? ldcs4(p + 15 * W4) : make_float4(0.f, 0.f, 0.f, 0.f);

    // tree max over the 16 row values
    #pragma unroll
    for (int s = 8; s >= 1; s >>= 1)
        #pragma unroll
        for (int i = 0; i < s; ++i)
            r[i] = fmax4(r[i], r[i + s]);

    sv[4 * tid + 0] = r[0].x;
    sv[4 * tid + 1] = r[0].y;
    sv[4 * tid + 2] = r[0].z;
    sv[4 * tid + 3] = r[0].w;
    __syncthreads();

    if (tid < 96) {                       // warps 0,1,2
        float m = 0.f;
        if (tid < BC) {
            const int w0 = tid * BSTR - 1;
            const int ws = (w0 < 0) ? 0 : w0;
            const int we = (w0 + BHW < WW) ? (w0 + BHW) : WW;
            for (int w = ws; w < we; ++w) m = fmaxf(m, sv[w]);
        }
        unsigned b = __ballot_sync(0xFFFFFFFFu, m > THRESH);
        if ((tid & 31) == 0) sbm[tid >> 5] = b;
    }
    __syncthreads();

    if (tid < 3) g_bitmap[cta * 3 + tid] = sbm[tid];
    if (tid == 0)
        g_count[cta] = (unsigned)(__popc(sbm[0]) + __popc(sbm[1]) + __popc(sbm[2]));
}

// ---------------------------------------------------------------------------
// K2: single-CTA exclusive scan over the 2336 per-row counts; emits g_total.
// ---------------------------------------------------------------------------
#define SCAN_T   256
#define SCAN_PER ((NROW + SCAN_T - 1) / SCAN_T)   // 10

__global__ __launch_bounds__(SCAN_T) void scan_kernel()
{
    __shared__ unsigned partial[SCAN_T];
    const int tid = threadIdx.x;

    unsigned local[SCAN_PER];
    unsigned sum = 0;
    #pragma unroll
    for (int i = 0; i < SCAN_PER; ++i) {
        int idx = tid * SCAN_PER + i;
        unsigned v = (idx < NROW) ? g_count[idx] : 0u;
        local[i] = sum;                 // exclusive within my chunk
        sum += v;
    }
    partial[tid] = sum;
    __syncthreads();

    for (int off = 1; off < SCAN_T; off <<= 1) {
        unsigned t = (tid >= off) ? partial[tid - off] : 0u;
        __syncthreads();
        partial[tid] += t;
        __syncthreads();
    }
    unsigned base = (tid > 0) ? partial[tid - 1] : 0u;

    #pragma unroll
    for (int i = 0; i < SCAN_PER; ++i) {
        int idx = tid * SCAN_PER + i;
        if (idx < NROW) g_offset[idx] = base + local[i];
    }
    if (tid == SCAN_T - 1) g_total = partial[tid];
}

// ---------------------------------------------------------------------------
// Position -> (n, bh, bw) resolution.
// Fast path (total == NBLK): identity divmod. General path: binary search
// last row with offset <= p, then select the rank-th set bit of the bitmap.
// ---------------------------------------------------------------------------
__device__ __forceinline__ int nth_set_bit(unsigned w, int n)  // n-th (0-based)
{
    return (int)__fns(w, 0, n + 1);
}

__device__ __forceinline__ void resolve_pos(unsigned p, unsigned total,
                                            float* t /*[3]*/)
{
    if (p >= total) { t[0] = -1.f; t[1] = -1.f; t[2] = -1.f; return; }

    if (total == NBLK) {   // dense: active block index == block index
        unsigned n = p / BC2;
        unsigned r = p - n * BC2;
        t[0] = (float)n;
        t[1] = (float)(r / BC);
        t[2] = (float)(r % BC);
        return;
    }

    int lo = 0, hi = NROW - 1;
    while (lo < hi) {
        int mid = (lo + hi + 1) >> 1;
        if (g_offset[mid] <= p) lo = mid; else hi = mid - 1;
    }
    int row = lo;
    int rank = (int)(p - g_offset[row]);

    unsigned w0 = g_bitmap[row * 3 + 0];
    unsigned w1 = g_bitmap[row * 3 + 1];
    unsigned w2 = g_bitmap[row * 3 + 2];
    int c0 = __popc(w0), c1 = __popc(w1);
    int bw;
    if (rank < c0)            bw = nth_set_bit(w0, rank);
    else if (rank - c0 < c1)  bw = 32 + nth_set_bit(w1, rank - c0);
    else                      bw = 64 + nth_set_bit(w2, rank - c0 - c1);

    t[0] = (float)(row / BC);
    t[1] = (float)(row % BC);
    t[2] = (float)bw;
}

// ---------------------------------------------------------------------------
// K3: output-driven write. One thread per float4 output slot (4 elements,
// spanning at most 2 consecutive positions). Dense coalesced 16B stores;
// -1 tail handled in the same pass — no fill kernel.
// ---------------------------------------------------------------------------
__global__ __launch_bounds__(256) void write_kernel(float4* __restrict__ out)
{
    const int slot = blockIdx.x * 256 + threadIdx.x;
    if (slot >= OUT_VEC4) return;

    const unsigned total = g_total;
    const unsigned e0 = (unsigned)slot * 4u;
    const unsigned p0 = e0 / 3u;

    float t0[3], t1[3];
    resolve_pos(p0, total, t0);
    resolve_pos(p0 + 1u, total, t1);

    float v[4];
    #pragma unroll
    for (int k = 0; k < 4; ++k) {
        unsigned e = e0 + (unsigned)k;
        unsigned p = e / 3u;
        unsigned c = e - p * 3u;
        v[k] = (p == p0) ? t0[c] : t1[c];
    }
    out[slot] = make_float4(v[0], v[1], v[2], v[3]);
}

// ---------------------------------------------------------------------------
extern "C" void kernel_launch(void* const* d_in, const int* in_sizes, int n_in,
                              void* d_out, int out_size)
{
    const float* mask = (const float*)d_in[0];

    pool_kernel<<<NROW, 256>>>(mask);
    scan_kernel<<<1, SCAN_T>>>();
    write_kernel<<<(OUT_VEC4 + 255) / 256, 256>>>((float4*)d_out);
}